// round 2
// baseline (speedup 1.0000x reference)
#include <cuda_runtime.h>
#include <cstdint>

#define NB 2
#define NN 32768
#define NC 64
#define NPT (NB * NN)

// ------------------------- device scratch (no allocs) -------------------------
__device__ float d_fT[NPT * NC];          // point-major current feature [pt][c]
__device__ float d_x[NPT * NC];           // attention output (pre-norm)  [pt][c]
__device__ unsigned char d_cls[NPT];      // argmax2 class s(b,n) in [0,16)
__device__ int d_seq[16 * 16];            // walk sequences per class
__device__ float d_A[64 * 64];            // Wq^T Wk (per layer)
__device__ float d_gvec[64];
__device__ float d_c0;
__device__ float d_PR[32 * 64 * 32];      // [cls][c][i32]  (i<16: P_i[c], i>=16: R_{i-16}[c])
__device__ float d_Vw[32 * 16 * 64];      // [cls][i][c]
__device__ float d_pb[32 * 32];           // [cls][i32]  (pb_i | rb_j)
__device__ float d_m[32 * 16];            // row max over 16 walk cols
__device__ float d_S16[32 * 16];          // sum exp over 16 walk cols
__device__ float d_Eii[32 * 16];          // exp(sim_ii - m_i)
__device__ float d_psum[64 * 128];
__device__ float d_psq[64 * 128];
__device__ float d_scale[64];
__device__ float d_shift[64];

// ------------------------- kT: transpose feature -> point-major -------------------------
__global__ void kT(const float* __restrict__ feat) {
    int bI = blockIdx.x;                  // 0..2047
    int b = bI >> 10;
    int n0 = (bI & 1023) * 32;
    __shared__ float sh[64 * 33];
    int t = threadIdx.x;
#pragma unroll
    for (int k = 0; k < 8; k++) {
        int idx = t + k * 256;            // 2048 = 64c x 32n
        int c = idx >> 5, col = idx & 31;
        sh[c * 33 + col] = feat[(b * 64 + c) * NN + n0 + col];
    }
    __syncthreads();
    int p = t >> 3, c8 = (t & 7) * 8;
#pragma unroll
    for (int j = 0; j < 8; j++) {
        d_fT[(b * NN + n0 + p) * 64 + c8 + j] = sh[(c8 + j) * 33 + p];
    }
}

// ------------------------- k0: per-point argmax2 class (one warp per point) -------------------------
__global__ void k0(const int* __restrict__ knn) {
    int w = threadIdx.x >> 5, lane = threadIdx.x & 31;
    int pt = blockIdx.x * 8 + w;
    int b = pt >> 15, n = pt & 32767;
    __shared__ __align__(16) float selfv[8][64];
    __shared__ float simsh[8][16];

    float2 fv = *(const float2*)&d_fT[pt * 64 + lane * 2];
    selfv[w][lane * 2] = fv.x;
    selfv[w][lane * 2 + 1] = fv.y;
    __syncwarp();

    int j = lane & 15, half = lane >> 4;
    int nb = __ldg(&knn[(b * NN + n) * 16 + j]);
    const float* nrow = &d_fT[(b * NN + nb) * 64 + half * 32];
    const float* srow = &selfv[w][half * 32];
    float part = 0.f;
#pragma unroll
    for (int c = 0; c < 32; c += 4) {
        float4 nv = *(const float4*)(nrow + c);
        float4 sv = *(const float4*)(srow + c);
        part += nv.x * sv.x + nv.y * sv.y + nv.z * sv.z + nv.w * sv.w;
    }
    float sim = part + __shfl_xor_sync(0xffffffffu, part, 16);
    if (half == 0) simsh[w][j] = sim;
    __syncwarp();

    if (lane == 0) {
        // stable top-2 (ties -> lower index first), matching jax.lax.top_k
        float v1 = -1e30f; int i1 = 0;
        for (int jj = 0; jj < 16; jj++) {
            float v = simsh[w][jj];
            if (v > v1) { v1 = v; i1 = jj; }
        }
        float v2 = -1e30f; int i2 = 0;
        for (int jj = 0; jj < 16; jj++) {
            if (jj == i1) continue;
            float v = simsh[w][jj];
            if (v > v2) { v2 = v; i2 = jj; }
        }
        d_cls[pt] = (unsigned char)i2;
    }
}

// ------------------------- kseq: build 16 walk sequences -------------------------
__global__ void kseq() {
    int s = threadIdx.x;
    if (s < 16) {
        int cur = s;
        d_seq[s * 16] = s;
        for (int t = 1; t < 16; t++) {
            cur = (int)d_cls[cur];        // g(r) = class of point r in batch 0
            d_seq[s * 16 + t] = cur;
        }
    }
}

// ------------------------- kA: A = Wq^T Wk, gvec, c0 (per layer) -------------------------
__global__ void kA(const float* __restrict__ Wq, const float* __restrict__ Wk,
                   const float* __restrict__ bq, const float* __restrict__ bk, int li) {
    const float* wq = Wq + li * 4096;
    const float* wk = Wk + li * 4096;
    const float* bqv = bq + li * 64;
    const float* bkv = bk + li * 64;
    int t = threadIdx.x;
    for (int idx = t; idx < 4096; idx += 256) {
        int c = idx >> 6, cp = idx & 63;
        float a = 0.f;
        for (int d = 0; d < 64; d++) a += wq[d * 64 + c] * wk[d * 64 + cp];
        d_A[idx] = a;
    }
    if (t < 64) {
        float g = 0.f;
        for (int d = 0; d < 64; d++) g += bqv[d] * wk[d * 64 + t] + bkv[d] * wq[d * 64 + t];
        d_gvec[t] = g;
    }
    if (t == 0) {
        float c0 = 0.f;
        for (int d = 0; d < 64; d++) c0 += bqv[d] * bkv[d];
        d_c0 = c0;
    }
}

// ------------------------- k1: per-(b,s) class tables (32 blocks) -------------------------
__global__ void k1(const float* __restrict__ Wq, const float* __restrict__ bq,
                   const float* __restrict__ Wk, const float* __restrict__ bk,
                   const float* __restrict__ Wv, const float* __restrict__ bv, int li) {
    int cls = blockIdx.x;
    int b = cls >> 4, s = cls & 15;
    const float* wq = Wq + li * 4096;
    const float* wk = Wk + li * 4096;
    const float* wv = Wv + li * 4096;
    const float* bqv = bq + li * 64;
    const float* bkv = bk + li * 64;
    const float* bvv = bv + li * 64;

    __shared__ float Wf[16 * 64], Qw[16 * 64], Kw[16 * 64];
    __shared__ float simm[16 * 16];
    int t = threadIdx.x;

    for (int idx = t; idx < 1024; idx += 256) {
        int i = idx >> 6, c = idx & 63;
        int p = d_seq[s * 16 + i];
        Wf[idx] = d_fT[(b * NN + p) * 64 + c];
    }
    __syncthreads();

    for (int idx = t; idx < 1024; idx += 256) {
        int i = idx >> 6, d = idx & 63;
        float aq = bqv[d], ak = bkv[d], av = bvv[d];
        for (int c = 0; c < 64; c++) {
            float wf = Wf[i * 64 + c];
            aq += wq[d * 64 + c] * wf;
            ak += wk[d * 64 + c] * wf;
            av += wv[d * 64 + c] * wf;
        }
        Qw[idx] = aq;
        Kw[idx] = ak;
        d_Vw[cls * 1024 + idx] = av;
    }
    __syncthreads();

    for (int idx = t; idx < 1024; idx += 256) {
        int i = idx >> 6, c = idx & 63;
        float ap = 0.f, ar = 0.f;
        for (int d = 0; d < 64; d++) {
            ap += Qw[i * 64 + d] * wk[d * 64 + c];
            ar += Kw[i * 64 + d] * wq[d * 64 + c];
        }
        d_PR[cls * 2048 + c * 32 + i] = ap;
        d_PR[cls * 2048 + c * 32 + 16 + i] = ar;
    }
    if (t < 32) {
        int i = t & 15;
        float acc = 0.f;
        if (t < 16) { for (int d = 0; d < 64; d++) acc += Qw[i * 64 + d] * bkv[d]; }
        else        { for (int d = 0; d < 64; d++) acc += Kw[i * 64 + d] * bqv[d]; }
        d_pb[cls * 32 + t] = acc;
    }
    if (t < 256) {
        int i = t >> 4, jj = t & 15;
        float a = 0.f;
        for (int d = 0; d < 64; d++) a += Qw[i * 64 + d] * Kw[jj * 64 + d];
        simm[t] = a;
    }
    __syncthreads();
    if (t < 16) {
        float m = -1e30f;
        for (int jj = 0; jj < 16; jj++) m = fmaxf(m, simm[t * 16 + jj]);
        float S = 0.f;
        for (int jj = 0; jj < 16; jj++) S += __expf(simm[t * 16 + jj] - m);
        d_m[cls * 16 + t] = m;
        d_S16[cls * 16 + t] = S;
        d_Eii[cls * 16 + t] = __expf(simm[t * 16 + t] - m);
    }
}

// ------------------------- k2: main per-point kernel (warp = 4 points) -------------------------
__global__ void __launch_bounds__(256) k2(const float* __restrict__ Wv,
                                          const float* __restrict__ bv, int li) {
    __shared__ __align__(16) float As[64 * 68];
    __shared__ __align__(16) float Ws[64 * 68];
    __shared__ __align__(16) float sfv[8][4][64];
    int t = threadIdx.x;
    const float* wv = Wv + li * 4096;

    for (int idx = t; idx < 4096; idx += 256) {
        int r = idx >> 6, c = idx & 63;
        As[r * 68 + c] = d_A[idx];
        Ws[r * 68 + c] = __ldg(&wv[idx]);
    }
    __syncthreads();

    int wid = t >> 5, lane = t & 31;
    int base = blockIdx.x * 32 + wid * 4;

    int cls[4];
    float qk[4];
#pragma unroll
    for (int q = 0; q < 4; q++) {
        int pt = base + q;
        float2 fv = *(const float2*)&d_fT[pt * 64 + lane * 2];
        sfv[wid][q][lane * 2] = fv.x;
        sfv[wid][q][lane * 2 + 1] = fv.y;
        cls[q] = ((pt >> 15) << 4) | (int)d_cls[pt];
    }
    __syncwarp();

    float u0[4] = {0, 0, 0, 0}, u1[4] = {0, 0, 0, 0};
    float v0[4] = {0, 0, 0, 0}, v1[4] = {0, 0, 0, 0};
    const float* A0 = &As[lane * 68];
    const float* A1 = &As[(lane + 32) * 68];
    const float* W0 = &Ws[lane * 68];
    const float* W1 = &Ws[(lane + 32) * 68];
#pragma unroll
    for (int c = 0; c < 64; c += 4) {
        float4 a0 = *(const float4*)(A0 + c);
        float4 a1 = *(const float4*)(A1 + c);
        float4 b0 = *(const float4*)(W0 + c);
        float4 b1 = *(const float4*)(W1 + c);
#pragma unroll
        for (int q = 0; q < 4; q++) {
            float4 fq = *(const float4*)&sfv[wid][q][c];
            u0[q] += a0.x * fq.x + a0.y * fq.y + a0.z * fq.z + a0.w * fq.w;
            u1[q] += a1.x * fq.x + a1.y * fq.y + a1.z * fq.z + a1.w * fq.w;
            v0[q] += b0.x * fq.x + b0.y * fq.y + b0.z * fq.z + b0.w * fq.w;
            v1[q] += b1.x * fq.x + b1.y * fq.y + b1.z * fq.z + b1.w * fq.w;
        }
    }

    float gl0 = __ldg(&d_gvec[lane]);
    float gl1 = __ldg(&d_gvec[lane + 32]);
    float c0v = d_c0;
    float bv0 = __ldg(&bv[li * 64 + lane]);
    float bv1 = __ldg(&bv[li * 64 + lane + 32]);

#pragma unroll
    for (int q = 0; q < 4; q++) {
        float fl0 = sfv[wid][q][lane];
        float fl1 = sfv[wid][q][lane + 32];
        float part = (u0[q] + gl0) * fl0 + (u1[q] + gl1) * fl1;
#pragma unroll
        for (int off = 16; off; off >>= 1) part += __shfl_xor_sync(0xffffffffu, part, off);
        qk[q] = part + c0v;   // Q_c . K_c
    }

#pragma unroll
    for (int q = 0; q < 4; q++) {
        const float* PRb = &d_PR[cls[q] * 2048];
        const float* fq = sfv[wid][q];
        float dot = 0.f;
#pragma unroll 8
        for (int c = 0; c < 64; c++) dot += __ldg(&PRb[c * 32 + lane]) * fq[c];
        dot += __ldg(&d_pb[cls[q] * 32 + lane]);
        // lane<16: sim[i][16];  lane>=16: sim[16][j]

        float dval = 0.f;
        if (lane < 16) {
            float mi = __ldg(&d_m[cls[q] * 16 + lane]);
            float S  = __ldg(&d_S16[cls[q] * 16 + lane]);
            float E  = __ldg(&d_Eii[cls[q] * 16 + lane]);
            dval = E / (S + __expf(dot - mi));
        }
        // center-row softmax diagonal
        float hv = (lane >= 16) ? dot : -1e30f;
#pragma unroll
        for (int off = 16; off; off >>= 1) hv = fmaxf(hv, __shfl_xor_sync(0xffffffffu, hv, off));
        float m16 = fmaxf(hv, qk[q]);
        float ev = (lane >= 16) ? __expf(dot - m16) : 0.f;
#pragma unroll
        for (int off = 16; off; off >>= 1) ev += __shfl_xor_sync(0xffffffffu, ev, off);
        float eq = __expf(qk[q] - m16);
        float d16 = eq / (ev + eq);

        float o0 = d16 * (v0[q] + bv0);
        float o1 = d16 * (v1[q] + bv1);
        const float* Vb = &d_Vw[cls[q] * 1024];
#pragma unroll
        for (int i = 0; i < 16; i++) {
            float di = __shfl_sync(0xffffffffu, dval, i);
            o0 += di * __ldg(&Vb[i * 64 + lane]);
            o1 += di * __ldg(&Vb[i * 64 + lane + 32]);
        }
        int pt = base + q;
        d_x[pt * 64 + lane] = o0;
        d_x[pt * 64 + lane + 32] = o1;
    }
}

// ------------------------- k3a/k3b: deterministic batch-norm stats -------------------------
__global__ void k3a() {
    int t = threadIdx.x;
    int c = t & 63, g = t >> 6;
    int p0 = blockIdx.x * 512;
    float s = 0.f, sq = 0.f;
    for (int k = 0; k < 128; k++) {
        float v = d_x[(p0 + g + k * 4) * 64 + c];
        s += v;
        sq += v * v;
    }
    __shared__ float shs[256], shq[256];
    shs[t] = s;
    shq[t] = sq;
    __syncthreads();
    if (t < 64) {
        float S = shs[t] + shs[t + 64] + shs[t + 128] + shs[t + 192];
        float Q = shq[t] + shq[t + 64] + shq[t + 128] + shq[t + 192];
        d_psum[t * 128 + blockIdx.x] = S;
        d_psq[t * 128 + blockIdx.x] = Q;
    }
}

__global__ void k3b(const float* __restrict__ gamma, const float* __restrict__ beta, int li) {
    int c = threadIdx.x;
    if (c < 64) {
        float S = 0.f, Q = 0.f;
        for (int k = 0; k < 128; k++) {
            S += d_psum[c * 128 + k];
            Q += d_psq[c * 128 + k];
        }
        float mean = S * (1.f / 65536.f);
        float var = Q * (1.f / 65536.f) - mean * mean;
        float sc = gamma[li * 64 + c] / sqrtf(var + 1e-5f);
        d_scale[c] = sc;
        d_shift[c] = beta[li * 64 + c] - sc * mean;
    }
}

// ------------------------- k4: norm + relu + residual; write d_out slice + update fT -------------------------
__global__ void k4(float* __restrict__ out, int li) {
    int p0 = blockIdx.x * 32;
    int b = p0 >> 15, n0 = p0 & 32767;
    __shared__ float sh[64 * 33];
    int t = threadIdx.x;
#pragma unroll
    for (int k = 0; k < 8; k++) {
        int idx = t + k * 256;            // 2048 = 32pts x 64c
        int p = idx >> 6, c = idx & 63;
        int a = (p0 + p) * 64 + c;
        float xv = d_x[a];
        float fo = d_fT[a];
        float y = fmaxf(d_scale[c] * xv + d_shift[c], 0.f);
        float fn = fo + y;
        d_fT[a] = fn;
        sh[c * 33 + p] = fn;
    }
    __syncthreads();
    int r = t >> 5, col = t & 31;
#pragma unroll
    for (int k = 0; k < 8; k++) {
        int c = r + k * 8;
        out[((size_t)(b * 192 + li * 64 + c)) * NN + n0 + col] = sh[c * 33 + col];
    }
}

// ------------------------- launch -------------------------
extern "C" void kernel_launch(void* const* d_in, const int* in_sizes, int n_in,
                              void* d_out, int out_size) {
    const float* feature = (const float*)d_in[0];
    const int*   knn     = (const int*)d_in[1];
    const float* Wq      = (const float*)d_in[2];
    const float* bq      = (const float*)d_in[3];
    const float* Wk      = (const float*)d_in[4];
    const float* bk      = (const float*)d_in[5];
    const float* Wv      = (const float*)d_in[6];
    const float* bv      = (const float*)d_in[7];
    const float* gamma   = (const float*)d_in[8];
    const float* beta    = (const float*)d_in[9];
    float* out = (float*)d_out;

    kT<<<2048, 256>>>(feature);
    k0<<<8192, 256>>>(knn);
    kseq<<<1, 16>>>();
    for (int li = 0; li < 3; li++) {
        kA<<<1, 256>>>(Wq, Wk, bq, bk, li);
        k1<<<32, 256>>>(Wq, bq, Wk, bk, Wv, bv, li);
        k2<<<2048, 256>>>(Wv, bv, li);
        k3a<<<128, 256>>>();
        k3b<<<1, 64>>>(gamma, beta, li);
        k4<<<2048, 256>>>(out, li);
    }
}

// round 3
// speedup vs baseline: 1.0404x; 1.0404x over previous
#include <cuda_runtime.h>
#include <cstdint>

#define NB 2
#define NN 32768
#define NC 64
#define NPT (NB * NN)

typedef unsigned long long ull;

__device__ __forceinline__ ull pk2(float x, float y) {
    ull r; asm("mov.b64 %0, {%1,%2};" : "=l"(r) : "f"(x), "f"(y)); return r;
}
__device__ __forceinline__ float2 unpk(ull a) {
    float2 v; asm("mov.b64 {%0,%1}, %2;" : "=f"(v.x), "=f"(v.y) : "l"(a)); return v;
}
__device__ __forceinline__ ull f2fma(ull a, ull b, ull c) {
    ull d; asm("fma.rn.f32x2 %0, %1, %2, %3;" : "=l"(d) : "l"(a), "l"(b), "l"(c)); return d;
}

// ------------------------- device scratch (no allocs) -------------------------
__device__ __align__(16) float d_fT[NPT * NC];      // point-major current feature [pt][c]
__device__ __align__(16) float d_x[NPT * NC];       // attention output (pre-norm)  [pt][c]
__device__ unsigned char d_cls[NPT];                // argmax2 class s(b,n) in [0,16)
__device__ int d_seq[16 * 16];                      // walk sequences per class
__device__ __align__(16) float d_A[64 * 64];        // Wq^T Wk (per layer)
__device__ float d_gvec[64];
__device__ float d_c0;
__device__ __align__(16) float d_PR[32 * 32 * 64];  // [cls][i32][c]  (i<16: P_i row, i>=16: R_{i-16} row)
__device__ __align__(16) float d_Vw[32 * 16 * 64];  // [cls][i][pair]: interleaved (c, c+32) float2 pairs
__device__ float d_pb[32 * 32];                     // [cls][i32]  (pb_i | rb_j)
__device__ float d_m[32 * 16];                      // row max over 16 walk cols
__device__ float d_S16[32 * 16];                    // sum exp over 16 walk cols
__device__ float d_Eii[32 * 16];                    // exp(sim_ii - m_i)
__device__ float d_psum[64 * 128];
__device__ float d_psq[64 * 128];
__device__ float d_scale[64];
__device__ float d_shift[64];

// ------------------------- kT: transpose feature -> point-major -------------------------
__global__ void kT(const float* __restrict__ feat) {
    int bI = blockIdx.x;                  // 0..2047
    int b = bI >> 10;
    int n0 = (bI & 1023) * 32;
    __shared__ float sh[64 * 33];
    int t = threadIdx.x;
#pragma unroll
    for (int k = 0; k < 8; k++) {
        int idx = t + k * 256;            // 2048 = 64c x 32n
        int c = idx >> 5, col = idx & 31;
        sh[c * 33 + col] = feat[(b * 64 + c) * NN + n0 + col];
    }
    __syncthreads();
    int p = t >> 3, c8 = (t & 7) * 8;
#pragma unroll
    for (int j = 0; j < 8; j++) {
        d_fT[(b * NN + n0 + p) * 64 + c8 + j] = sh[(c8 + j) * 33 + p];
    }
}

// ------------------------- k0: per-point argmax2 class (one warp per point) -------------------------
__global__ void k0(const int* __restrict__ knn) {
    int w = threadIdx.x >> 5, lane = threadIdx.x & 31;
    int pt = blockIdx.x * 8 + w;
    int b = pt >> 15, n = pt & 32767;
    __shared__ __align__(16) float selfv[8][64];
    __shared__ float simsh[8][16];

    float2 fv = *(const float2*)&d_fT[pt * 64 + lane * 2];
    selfv[w][lane * 2] = fv.x;
    selfv[w][lane * 2 + 1] = fv.y;
    __syncwarp();

    int j = lane & 15, half = lane >> 4;
    int nb = __ldg(&knn[(b * NN + n) * 16 + j]);
    const float* nrow = &d_fT[(b * NN + nb) * 64 + half * 32];
    const float* srow = &selfv[w][half * 32];
    float part = 0.f;
#pragma unroll
    for (int c = 0; c < 32; c += 4) {
        float4 nv = *(const float4*)(nrow + c);
        float4 sv = *(const float4*)(srow + c);
        part += nv.x * sv.x + nv.y * sv.y + nv.z * sv.z + nv.w * sv.w;
    }
    float sim = part + __shfl_xor_sync(0xffffffffu, part, 16);
    if (half == 0) simsh[w][j] = sim;
    __syncwarp();

    if (lane == 0) {
        // stable top-2 (ties -> lower index first), matching jax.lax.top_k
        float v1 = -1e30f; int i1 = 0;
        for (int jj = 0; jj < 16; jj++) {
            float v = simsh[w][jj];
            if (v > v1) { v1 = v; i1 = jj; }
        }
        float v2 = -1e30f; int i2 = 0;
        for (int jj = 0; jj < 16; jj++) {
            if (jj == i1) continue;
            float v = simsh[w][jj];
            if (v > v2) { v2 = v; i2 = jj; }
        }
        d_cls[pt] = (unsigned char)i2;
    }
}

// ------------------------- kseq: build 16 walk sequences -------------------------
__global__ void kseq() {
    int s = threadIdx.x;
    if (s < 16) {
        int cur = s;
        d_seq[s * 16] = s;
        for (int t = 1; t < 16; t++) {
            cur = (int)d_cls[cur];        // g(r) = class of point r in batch 0
            d_seq[s * 16 + t] = cur;
        }
    }
}

// ------------------------- kA: A = Wq^T Wk, gvec, c0 (per layer) — 16 blocks -------------------------
__global__ void kA(const float* __restrict__ Wq, const float* __restrict__ Wk,
                   const float* __restrict__ bq, const float* __restrict__ bk, int li) {
    const float* wq = Wq + li * 4096;
    const float* wk = Wk + li * 4096;
    __shared__ float sq[64 * 64], sk[64 * 64];
    int t = threadIdx.x;
    for (int idx = t; idx < 4096; idx += 256) {
        sq[idx] = __ldg(&wq[idx]);
        sk[idx] = __ldg(&wk[idx]);
    }
    __syncthreads();
    int e = blockIdx.x * 256 + t;
    int c = e >> 6, cp = e & 63;
    float a = 0.f;
#pragma unroll 8
    for (int d = 0; d < 64; d++) a += sq[d * 64 + c] * sk[d * 64 + cp];
    d_A[e] = a;
    if (blockIdx.x == 0) {
        const float* bqv = bq + li * 64;
        const float* bkv = bk + li * 64;
        if (t < 64) {
            float g = 0.f;
            for (int d = 0; d < 64; d++) g += __ldg(&bqv[d]) * sk[d * 64 + t] + __ldg(&bkv[d]) * sq[d * 64 + t];
            d_gvec[t] = g;
        }
        if (t == 0) {
            float c0 = 0.f;
            for (int d = 0; d < 64; d++) c0 += __ldg(&bqv[d]) * __ldg(&bkv[d]);
            d_c0 = c0;
        }
    }
}

// ------------------------- k1: per-(b,s) class tables (32 blocks) -------------------------
__global__ void k1(const float* __restrict__ Wq, const float* __restrict__ bq,
                   const float* __restrict__ Wk, const float* __restrict__ bk,
                   const float* __restrict__ Wv, const float* __restrict__ bv, int li) {
    int cls = blockIdx.x;
    int b = cls >> 4, s = cls & 15;
    const float* wq = Wq + li * 4096;
    const float* wk = Wk + li * 4096;
    const float* wv = Wv + li * 4096;
    const float* bqv = bq + li * 64;
    const float* bkv = bk + li * 64;
    const float* bvv = bv + li * 64;

    __shared__ float Wf[16 * 64], Qw[16 * 64], Kw[16 * 64];
    __shared__ float simm[16 * 16];
    __shared__ __align__(16) float sqT[64 * 68], skT[64 * 68];  // transposed weights [c][d]
    int t = threadIdx.x;

    for (int idx = t; idx < 4096; idx += 256) {
        int d = idx >> 6, c = idx & 63;
        sqT[c * 68 + d] = __ldg(&wq[idx]);
        skT[c * 68 + d] = __ldg(&wk[idx]);
    }
    for (int idx = t; idx < 1024; idx += 256) {
        int i = idx >> 6, c = idx & 63;
        int p = d_seq[s * 16 + i];
        Wf[idx] = d_fT[(b * NN + p) * 64 + c];
    }
    __syncthreads();

    for (int idx = t; idx < 1024; idx += 256) {
        int i = idx >> 6, d = idx & 63;
        float aq = __ldg(&bqv[d]), ak = __ldg(&bkv[d]), av = __ldg(&bvv[d]);
#pragma unroll
        for (int c = 0; c < 64; c += 4) {
            float4 q4 = __ldg((const float4*)&wq[d * 64 + c]);
            float4 k4 = __ldg((const float4*)&wk[d * 64 + c]);
            float4 v4 = __ldg((const float4*)&wv[d * 64 + c]);
            float4 wf = *(const float4*)&Wf[i * 64 + c];
            aq += q4.x * wf.x + q4.y * wf.y + q4.z * wf.z + q4.w * wf.w;
            ak += k4.x * wf.x + k4.y * wf.y + k4.z * wf.z + k4.w * wf.w;
            av += v4.x * wf.x + v4.y * wf.y + v4.z * wf.z + v4.w * wf.w;
        }
        Qw[idx] = aq;
        Kw[idx] = ak;
        // interleaved pair layout: (c, c+32) adjacent
        int pos = (d < 32) ? (2 * d) : (2 * (d - 32) + 1);
        d_Vw[cls * 1024 + i * 64 + pos] = av;
    }
    __syncthreads();

    for (int idx = t; idx < 1024; idx += 256) {
        int i = idx >> 6, c = idx & 63;
        float ap = 0.f, ar = 0.f;
#pragma unroll
        for (int d = 0; d < 64; d += 4) {
            float4 kk = *(const float4*)&skT[c * 68 + d];
            float4 qq = *(const float4*)&sqT[c * 68 + d];
            float4 qw = *(const float4*)&Qw[i * 64 + d];
            float4 kw = *(const float4*)&Kw[i * 64 + d];
            ap += qw.x * kk.x + qw.y * kk.y + qw.z * kk.z + qw.w * kk.w;
            ar += kw.x * qq.x + kw.y * qq.y + kw.z * qq.z + kw.w * qq.w;
        }
        d_PR[cls * 2048 + i * 64 + c] = ap;          // P_i row
        d_PR[cls * 2048 + (16 + i) * 64 + c] = ar;   // R_j row
    }
    if (t < 32) {
        int i = t & 15;
        float acc = 0.f;
        if (t < 16) { for (int d = 0; d < 64; d++) acc += Qw[i * 64 + d] * __ldg(&bkv[d]); }
        else        { for (int d = 0; d < 64; d++) acc += Kw[i * 64 + d] * __ldg(&bqv[d]); }
        d_pb[cls * 32 + t] = acc;
    }
    {
        int i = t >> 4, jj = t & 15;
        float a = 0.f;
        for (int d = 0; d < 64; d++) a += Qw[i * 64 + d] * Kw[jj * 64 + d];
        simm[t] = a;
    }
    __syncthreads();
    if (t < 16) {
        float m = -1e30f;
        for (int jj = 0; jj < 16; jj++) m = fmaxf(m, simm[t * 16 + jj]);
        float S = 0.f;
        for (int jj = 0; jj < 16; jj++) S += __expf(simm[t * 16 + jj] - m);
        d_m[cls * 16 + t] = m;
        d_S16[cls * 16 + t] = S;
        d_Eii[cls * 16 + t] = __expf(simm[t * 16 + t] - m);
    }
}

// ------------------------- k2: main per-point kernel (warp = 4 points, f32x2 packed) -------------------------
__global__ void __launch_bounds__(256, 3) k2(const float* __restrict__ Wv,
                                             const float* __restrict__ bv, int li) {
    __shared__ __align__(16) float As[64 * 68];
    __shared__ __align__(16) float Ws[64 * 68];
    __shared__ __align__(16) float sfv[8][4][64];
    int t = threadIdx.x;
    const float* wv = Wv + li * 4096;

    for (int idx = t; idx < 4096; idx += 256) {
        int r = idx >> 6, c = idx & 63;
        As[r * 68 + c] = d_A[idx];
        Ws[r * 68 + c] = __ldg(&wv[idx]);
    }
    __syncthreads();

    int wid = t >> 5, lane = t & 31;
    int base = blockIdx.x * 32 + wid * 4;

    int cls[4];
    float qk[4];
#pragma unroll
    for (int q = 0; q < 4; q++) {
        int pt = base + q;
        float2 fv = *(const float2*)&d_fT[pt * 64 + lane * 2];
        sfv[wid][q][lane * 2] = fv.x;
        sfv[wid][q][lane * 2 + 1] = fv.y;
        cls[q] = ((pt >> 15) << 4) | (int)d_cls[pt];
    }
    __syncwarp();

    // u = A.f (c = lane / lane+32 components), v = Wv.f — packed over c-pairs
    ull u0[4] = {0, 0, 0, 0}, u1[4] = {0, 0, 0, 0};
    ull v0[4] = {0, 0, 0, 0}, v1[4] = {0, 0, 0, 0};
    const float* A0 = &As[lane * 68];
    const float* A1 = &As[(lane + 32) * 68];
    const float* W0 = &Ws[lane * 68];
    const float* W1 = &Ws[(lane + 32) * 68];
#pragma unroll
    for (int c = 0; c < 64; c += 4) {
        float4 a0 = *(const float4*)(A0 + c);
        float4 a1 = *(const float4*)(A1 + c);
        float4 b0 = *(const float4*)(W0 + c);
        float4 b1 = *(const float4*)(W1 + c);
        ull a0l = pk2(a0.x, a0.y), a0h = pk2(a0.z, a0.w);
        ull a1l = pk2(a1.x, a1.y), a1h = pk2(a1.z, a1.w);
        ull w0l = pk2(b0.x, b0.y), w0h = pk2(b0.z, b0.w);
        ull w1l = pk2(b1.x, b1.y), w1h = pk2(b1.z, b1.w);
#pragma unroll
        for (int q = 0; q < 4; q++) {
            float4 f = *(const float4*)&sfv[wid][q][c];
            ull fl = pk2(f.x, f.y), fh = pk2(f.z, f.w);
            u0[q] = f2fma(a0l, fl, u0[q]); u0[q] = f2fma(a0h, fh, u0[q]);
            u1[q] = f2fma(a1l, fl, u1[q]); u1[q] = f2fma(a1h, fh, u1[q]);
            v0[q] = f2fma(w0l, fl, v0[q]); v0[q] = f2fma(w0h, fh, v0[q]);
            v1[q] = f2fma(w1l, fl, v1[q]); v1[q] = f2fma(w1h, fh, v1[q]);
        }
    }

    float gl0 = __ldg(&d_gvec[lane]);
    float gl1 = __ldg(&d_gvec[lane + 32]);
    float c0v = d_c0;
    float bv0 = __ldg(&bv[li * 64 + lane]);
    float bv1 = __ldg(&bv[li * 64 + lane + 32]);

    float v0f[4], v1f[4];
#pragma unroll
    for (int q = 0; q < 4; q++) {
        float2 uu0 = unpk(u0[q]), uu1 = unpk(u1[q]);
        float2 vv0 = unpk(v0[q]), vv1 = unpk(v1[q]);
        v0f[q] = vv0.x + vv0.y;
        v1f[q] = vv1.x + vv1.y;
        float fl0 = sfv[wid][q][lane];
        float fl1 = sfv[wid][q][lane + 32];
        float part = (uu0.x + uu0.y + gl0) * fl0 + (uu1.x + uu1.y + gl1) * fl1;
#pragma unroll
        for (int off = 16; off; off >>= 1) part += __shfl_xor_sync(0xffffffffu, part, off);
        qk[q] = part + c0v;   // Q_c . K_c
    }

#pragma unroll
    for (int q = 0; q < 4; q++) {
        // cross terms: lane<16 -> sim[i][16]; lane>=16 -> sim[16][j]
        const float* PRrow = &d_PR[cls[q] * 2048 + lane * 64];
        ull acc0 = 0, acc1 = 0;
#pragma unroll
        for (int c = 0; c < 64; c += 4) {
            float4 p = __ldg((const float4*)(PRrow + c));
            float4 f = *(const float4*)&sfv[wid][q][c];
            acc0 = f2fma(pk2(p.x, p.y), pk2(f.x, f.y), acc0);
            acc1 = f2fma(pk2(p.z, p.w), pk2(f.z, f.w), acc1);
        }
        float2 aa = unpk(acc0), ab = unpk(acc1);
        float dot = aa.x + aa.y + ab.x + ab.y + __ldg(&d_pb[cls[q] * 32 + lane]);

        float dval = 0.f;
        if (lane < 16) {
            float mi = __ldg(&d_m[cls[q] * 16 + lane]);
            float S  = __ldg(&d_S16[cls[q] * 16 + lane]);
            float E  = __ldg(&d_Eii[cls[q] * 16 + lane]);
            dval = E / (S + __expf(dot - mi));
        }
        // center-row softmax diagonal
        float hv = (lane >= 16) ? dot : -1e30f;
#pragma unroll
        for (int off = 16; off; off >>= 1) hv = fmaxf(hv, __shfl_xor_sync(0xffffffffu, hv, off));
        float m16 = fmaxf(hv, qk[q]);
        float ev = (lane >= 16) ? __expf(dot - m16) : 0.f;
#pragma unroll
        for (int off = 16; off; off >>= 1) ev += __shfl_xor_sync(0xffffffffu, ev, off);
        float eq = __expf(qk[q] - m16);
        float d16 = eq / (ev + eq);

        ull oacc = pk2(d16 * (v0f[q] + bv0), d16 * (v1f[q] + bv1));
        const float2* Vb = (const float2*)&d_Vw[cls[q] * 1024];
#pragma unroll
        for (int i = 0; i < 16; i++) {
            float di = __shfl_sync(0xffffffffu, dval, i);
            float2 vb = __ldg(&Vb[i * 32 + lane]);
            oacc = f2fma(pk2(vb.x, vb.y), pk2(di, di), oacc);
        }
        float2 o = unpk(oacc);
        int pt = base + q;
        d_x[pt * 64 + lane] = o.x;
        d_x[pt * 64 + lane + 32] = o.y;
    }
}

// ------------------------- k3a/k3b: deterministic batch-norm stats -------------------------
__global__ void k3a() {
    int t = threadIdx.x;
    int c = t & 63, g = t >> 6;
    int p0 = blockIdx.x * 512;
    float s = 0.f, sq = 0.f;
    for (int k = 0; k < 128; k++) {
        float v = d_x[(p0 + g + k * 4) * 64 + c];
        s += v;
        sq += v * v;
    }
    __shared__ float shs[256], shq[256];
    shs[t] = s;
    shq[t] = sq;
    __syncthreads();
    if (t < 64) {
        float S = shs[t] + shs[t + 64] + shs[t + 128] + shs[t + 192];
        float Q = shq[t] + shq[t + 64] + shq[t + 128] + shq[t + 192];
        d_psum[t * 128 + blockIdx.x] = S;
        d_psq[t * 128 + blockIdx.x] = Q;
    }
}

__global__ void k3b(const float* __restrict__ gamma, const float* __restrict__ beta, int li) {
    int c = threadIdx.x;
    if (c < 64) {
        float S = 0.f, Q = 0.f;
        for (int k = 0; k < 128; k++) {
            S += d_psum[c * 128 + k];
            Q += d_psq[c * 128 + k];
        }
        float mean = S * (1.f / 65536.f);
        float var = Q * (1.f / 65536.f) - mean * mean;
        float sc = gamma[li * 64 + c] / sqrtf(var + 1e-5f);
        d_scale[c] = sc;
        d_shift[c] = beta[li * 64 + c] - sc * mean;
    }
}

// ------------------------- k4: norm + relu + residual; write d_out slice + update fT -------------------------
__global__ void k4(float* __restrict__ out, int li) {
    int p0 = blockIdx.x * 32;
    int b = p0 >> 15, n0 = p0 & 32767;
    __shared__ float sh[64 * 33];
    int t = threadIdx.x;
#pragma unroll
    for (int k = 0; k < 8; k++) {
        int idx = t + k * 256;            // 2048 = 32pts x 64c
        int p = idx >> 6, c = idx & 63;
        int a = (p0 + p) * 64 + c;
        float xv = d_x[a];
        float fo = d_fT[a];
        float y = fmaxf(d_scale[c] * xv + d_shift[c], 0.f);
        float fn = fo + y;
        d_fT[a] = fn;
        sh[c * 33 + p] = fn;
    }
    __syncthreads();
    int r = t >> 5, col = t & 31;
#pragma unroll
    for (int k = 0; k < 8; k++) {
        int c = r + k * 8;
        out[((size_t)(b * 192 + li * 64 + c)) * NN + n0 + col] = sh[c * 33 + col];
    }
}

// ------------------------- launch -------------------------
extern "C" void kernel_launch(void* const* d_in, const int* in_sizes, int n_in,
                              void* d_out, int out_size) {
    const float* feature = (const float*)d_in[0];
    const int*   knn     = (const int*)d_in[1];
    const float* Wq      = (const float*)d_in[2];
    const float* bq      = (const float*)d_in[3];
    const float* Wk      = (const float*)d_in[4];
    const float* bk      = (const float*)d_in[5];
    const float* Wv      = (const float*)d_in[6];
    const float* bv      = (const float*)d_in[7];
    const float* gamma   = (const float*)d_in[8];
    const float* beta    = (const float*)d_in[9];
    float* out = (float*)d_out;

    kT<<<2048, 256>>>(feature);
    k0<<<8192, 256>>>(knn);
    kseq<<<1, 16>>>();
    for (int li = 0; li < 3; li++) {
        kA<<<16, 256>>>(Wq, Wk, bq, bk, li);
        k1<<<32, 256>>>(Wq, bq, Wk, bk, Wv, bv, li);
        k2<<<2048, 256>>>(Wv, bv, li);
        k3a<<<128, 256>>>();
        k3b<<<1, 64>>>(gamma, beta, li);
        k4<<<2048, 256>>>(out, li);
    }
}

// round 4
// speedup vs baseline: 2.0911x; 2.0100x over previous
#include <cuda_runtime.h>
#include <cstdint>

#define NB 2
#define NN 32768
#define NC 64
#define NPT (NB * NN)
#define NBLK2 2080

typedef unsigned long long ull;

__device__ __forceinline__ ull pk2(float x, float y) {
    ull r; asm("mov.b64 %0, {%1,%2};" : "=l"(r) : "f"(x), "f"(y)); return r;
}
__device__ __forceinline__ float2 unpk(ull a) {
    float2 v; asm("mov.b64 {%0,%1}, %2;" : "=f"(v.x), "=f"(v.y) : "l"(a)); return v;
}
__device__ __forceinline__ ull f2fma(ull a, ull b, ull c) {
    ull d; asm("fma.rn.f32x2 %0, %1, %2, %3;" : "=l"(d) : "l"(a), "l"(b), "l"(c)); return d;
}

// ------------------------- device scratch (no allocs) -------------------------
__device__ __align__(16) float d_fT[NPT * NC];      // point-major current feature [pt][c]
__device__ __align__(16) float d_x[NPT * NC];       // attention output (pre-norm)  [pt][c]
__device__ unsigned char d_cls[NPT];                // argmax2 class s(b,n) in [0,16)
__device__ int d_seq[16 * 16];                      // walk sequences per class
__device__ __align__(16) float d_A[64 * 64];        // Wq^T Wk (per layer)
__device__ float d_gvec[64];
__device__ float d_c0;
__device__ __align__(16) float d_PR[32 * 64 * 32];  // [cls][c][i32]  c-major rows
__device__ __align__(16) float d_Vw[32 * 16 * 64];  // [cls][i][pair]: interleaved (c, c+32) float2
__device__ float d_pb[32 * 32];                     // [cls][i32]
__device__ float d_m[32 * 16];
__device__ float d_S16[32 * 16];
__device__ float d_Eii[32 * 16];
__device__ float d_psum[64 * 128];
__device__ float d_psq[64 * 128];
__device__ float d_scale[64];
__device__ float d_shift[64];
// sorting
__device__ int d_cnt[32];
__device__ int d_pos[32];
__device__ int d_order[NPT];
__device__ int d_bcls[NBLK2];
__device__ int d_bstart[NBLK2];
__device__ int d_bn[NBLK2];

// ------------------------- kT: transpose feature -> point-major (+zero counters) -------------------------
__global__ void kT(const float* __restrict__ feat) {
    int bI = blockIdx.x;                  // 0..2047
    int b = bI >> 10;
    int n0 = (bI & 1023) * 32;
    __shared__ float sh[64 * 33];
    int t = threadIdx.x;
    if (bI == 0 && t < 32) d_cnt[t] = 0;
#pragma unroll
    for (int k = 0; k < 8; k++) {
        int idx = t + k * 256;            // 2048 = 64c x 32n
        int c = idx >> 5, col = idx & 31;
        sh[c * 33 + col] = feat[(b * 64 + c) * NN + n0 + col];
    }
    __syncthreads();
    int p = t >> 3, c8 = (t & 7) * 8;
#pragma unroll
    for (int j = 0; j < 8; j++) {
        d_fT[(b * NN + n0 + p) * 64 + c8 + j] = sh[(c8 + j) * 33 + p];
    }
}

// ------------------------- k0: per-point argmax2 class (one warp per point) -------------------------
__global__ void k0(const int* __restrict__ knn) {
    int w = threadIdx.x >> 5, lane = threadIdx.x & 31;
    int pt = blockIdx.x * 8 + w;
    int b = pt >> 15, n = pt & 32767;
    __shared__ __align__(16) float selfv[8][64];
    __shared__ float simsh[8][16];

    float2 fv = *(const float2*)&d_fT[pt * 64 + lane * 2];
    selfv[w][lane * 2] = fv.x;
    selfv[w][lane * 2 + 1] = fv.y;
    __syncwarp();

    int j = lane & 15, half = lane >> 4;
    int nb = __ldg(&knn[(b * NN + n) * 16 + j]);
    const float* nrow = &d_fT[(b * NN + nb) * 64 + half * 32];
    const float* srow = &selfv[w][half * 32];
    float part = 0.f;
#pragma unroll
    for (int c = 0; c < 32; c += 4) {
        float4 nv = *(const float4*)(nrow + c);
        float4 sv = *(const float4*)(srow + c);
        part += nv.x * sv.x + nv.y * sv.y + nv.z * sv.z + nv.w * sv.w;
    }
    float sim = part + __shfl_xor_sync(0xffffffffu, part, 16);
    if (half == 0) simsh[w][j] = sim;
    __syncwarp();

    if (lane == 0) {
        float v1 = -1e30f; int i1 = 0;
        for (int jj = 0; jj < 16; jj++) {
            float v = simsh[w][jj];
            if (v > v1) { v1 = v; i1 = jj; }
        }
        float v2 = -1e30f; int i2 = 0;
        for (int jj = 0; jj < 16; jj++) {
            if (jj == i1) continue;
            float v = simsh[w][jj];
            if (v > v2) { v2 = v; i2 = jj; }
        }
        d_cls[pt] = (unsigned char)i2;
    }
}

// ------------------------- khist: bucket histogram -------------------------
__global__ void khist() {
    __shared__ int h[32];
    int t = threadIdx.x;
    if (t < 32) h[t] = 0;
    __syncthreads();
#pragma unroll
    for (int k = 0; k < 4; k++) {
        int pt = blockIdx.x * 1024 + k * 256 + t;
        int cls = ((pt >> 15) << 4) | (int)d_cls[pt];
        atomicAdd(&h[cls], 1);
    }
    __syncthreads();
    if (t < 32) atomicAdd(&d_cnt[t], h[t]);
}

// ------------------------- kscan: prefix sums + block table + walk sequences -------------------------
__global__ void kscan() {
    int t = threadIdx.x;  // 32 threads, 1 warp
    for (int e = t; e < NBLK2; e += 32) d_bcls[e] = -1;
    __syncthreads();
    int cnt = d_cnt[t];
    // inclusive scan of cnt
    int x = cnt;
#pragma unroll
    for (int off = 1; off < 32; off <<= 1) {
        int y = __shfl_up_sync(0xffffffffu, x, off);
        if (t >= off) x += y;
    }
    int ex = x - cnt;            // exclusive offset
    d_pos[t] = ex;
    int ent = (cnt + 31) >> 5;
    int z = ent;
#pragma unroll
    for (int off = 1; off < 32; off <<= 1) {
        int y = __shfl_up_sync(0xffffffffu, z, off);
        if (t >= off) z += y;
    }
    int eex = z - ent;
    for (int e = 0; e < ent; e++) {
        d_bcls[eex + e] = t;
        d_bstart[eex + e] = ex + e * 32;
        int rem = cnt - e * 32;
        d_bn[eex + e] = rem < 32 ? rem : 32;
    }
    // walk sequences (only needs d_cls[0..15])
    if (t < 16) {
        int cur = t;
        d_seq[t * 16] = t;
        for (int s = 1; s < 16; s++) {
            cur = (int)d_cls[cur];
            d_seq[t * 16 + s] = cur;
        }
    }
}

// ------------------------- kscatter: build sorted order -------------------------
__global__ void kscatter() {
    int t = threadIdx.x;
#pragma unroll
    for (int k = 0; k < 4; k++) {
        int pt = blockIdx.x * 1024 + k * 256 + t;
        int cls = ((pt >> 15) << 4) | (int)d_cls[pt];
        int pos = atomicAdd(&d_pos[cls], 1);
        d_order[pos] = pt;
    }
}

// ------------------------- kPre: per-layer tables. blocks 0-31: class tables; 32-63: A matrix -------------------------
__global__ void __launch_bounds__(256) kPre(const float* __restrict__ Wq, const float* __restrict__ bq,
                                            const float* __restrict__ Wk, const float* __restrict__ bk,
                                            const float* __restrict__ Wv, const float* __restrict__ bv, int li) {
    const float* wq = Wq + li * 4096;
    const float* wk = Wk + li * 4096;
    const float* wv = Wv + li * 4096;
    const float* bqv = bq + li * 64;
    const float* bkv = bk + li * 64;
    const float* bvv = bv + li * 64;
    __shared__ __align__(16) float shA[64 * 68];
    __shared__ __align__(16) float shB[64 * 68];
    __shared__ float Wf[1024], Qw[1024], Kw[1024];
    __shared__ float simm[256];
    int t = threadIdx.x;

    if (blockIdx.x >= 32) {
        // ---- A = Wq^T Wk (32 blocks x 128 entries) ----
        for (int idx = t; idx < 4096; idx += 256) {
            shA[idx] = __ldg(&wq[idx]);
            shB[idx] = __ldg(&wk[idx]);
        }
        __syncthreads();
        int base = (blockIdx.x - 32) * 128;
        if (t < 128) {
            int e = base + t;
            int c = e >> 6, cp = e & 63;
            float a = 0.f;
#pragma unroll 8
            for (int d = 0; d < 64; d++) a += shA[d * 64 + c] * shB[d * 64 + cp];
            d_A[e] = a;
        }
        if (blockIdx.x == 32) {
            if (t >= 128 && t < 192) {
                int c = t - 128;
                float g = 0.f;
                for (int d = 0; d < 64; d++) g += __ldg(&bqv[d]) * shB[d * 64 + c] + __ldg(&bkv[d]) * shA[d * 64 + c];
                d_gvec[c] = g;
            }
            if (t == 255) {
                float c0 = 0.f;
                for (int d = 0; d < 64; d++) c0 += __ldg(&bqv[d]) * __ldg(&bkv[d]);
                d_c0 = c0;
            }
        }
        return;
    }

    // ---- class tables (cls = blockIdx.x) ----
    int cls = blockIdx.x;
    int b = cls >> 4, s = cls & 15;

    for (int idx = t; idx < 4096; idx += 256) {
        int d = idx >> 6, c = idx & 63;
        shA[c * 68 + d] = __ldg(&wq[idx]);   // Wq^T
        shB[c * 68 + d] = __ldg(&wk[idx]);   // Wk^T
    }
    for (int idx = t; idx < 1024; idx += 256) {
        int i = idx >> 6, c = idx & 63;
        int p = d_seq[s * 16 + i];
        Wf[idx] = d_fT[(b * NN + p) * 64 + c];
    }
    __syncthreads();

    for (int idx = t; idx < 1024; idx += 256) {
        int i = idx >> 6, d = idx & 63;
        float aq = __ldg(&bqv[d]), ak = __ldg(&bkv[d]), av = __ldg(&bvv[d]);
#pragma unroll
        for (int c = 0; c < 64; c += 4) {
            float4 q4 = __ldg((const float4*)&wq[d * 64 + c]);
            float4 k4 = __ldg((const float4*)&wk[d * 64 + c]);
            float4 v4 = __ldg((const float4*)&wv[d * 64 + c]);
            float4 wf = *(const float4*)&Wf[i * 64 + c];
            aq += q4.x * wf.x + q4.y * wf.y + q4.z * wf.z + q4.w * wf.w;
            ak += k4.x * wf.x + k4.y * wf.y + k4.z * wf.z + k4.w * wf.w;
            av += v4.x * wf.x + v4.y * wf.y + v4.z * wf.z + v4.w * wf.w;
        }
        Qw[idx] = aq;
        Kw[idx] = ak;
        int pos = (d < 32) ? (2 * d) : (2 * (d - 32) + 1);   // interleaved (c,c+32)
        d_Vw[cls * 1024 + i * 64 + pos] = av;
    }
    __syncthreads();

    for (int idx = t; idx < 1024; idx += 256) {
        int i = idx >> 6, c = idx & 63;
        float ap = 0.f, ar = 0.f;
#pragma unroll
        for (int d = 0; d < 64; d += 4) {
            float4 kk = *(const float4*)&shB[c * 68 + d];
            float4 qq = *(const float4*)&shA[c * 68 + d];
            float4 qw = *(const float4*)&Qw[i * 64 + d];
            float4 kw = *(const float4*)&Kw[i * 64 + d];
            ap += qw.x * kk.x + qw.y * kk.y + qw.z * kk.z + qw.w * kk.w;
            ar += kw.x * qq.x + kw.y * qq.y + kw.z * qq.z + kw.w * qq.w;
        }
        d_PR[cls * 2048 + c * 32 + i] = ap;          // P_i  (c-major)
        d_PR[cls * 2048 + c * 32 + 16 + i] = ar;     // R_j
    }
    if (t < 32) {
        int i = t & 15;
        float acc = 0.f;
        if (t < 16) { for (int d = 0; d < 64; d++) acc += Qw[i * 64 + d] * __ldg(&bkv[d]); }
        else        { for (int d = 0; d < 64; d++) acc += Kw[i * 64 + d] * __ldg(&bqv[d]); }
        d_pb[cls * 32 + t] = acc;
    }
    {
        int i = t >> 4, jj = t & 15;
        float a = 0.f;
        for (int d = 0; d < 64; d++) a += Qw[i * 64 + d] * Kw[jj * 64 + d];
        simm[t] = a;
    }
    __syncthreads();
    if (t < 16) {
        float m = -1e30f;
        for (int jj = 0; jj < 16; jj++) m = fmaxf(m, simm[t * 16 + jj]);
        float S = 0.f;
        for (int jj = 0; jj < 16; jj++) S += __expf(simm[t * 16 + jj] - m);
        d_m[cls * 16 + t] = m;
        d_S16[cls * 16 + t] = S;
        d_Eii[cls * 16 + t] = __expf(simm[t * 16 + t] - m);
    }
}

// ------------------------- k2: main per-point kernel, class-sorted blocks -------------------------
__global__ void __launch_bounds__(256, 3) k2(const float* __restrict__ Wv,
                                             const float* __restrict__ bv, int li) {
    int cls = __ldg(&d_bcls[blockIdx.x]);
    if (cls < 0) return;
    int bstart = __ldg(&d_bstart[blockIdx.x]);
    int bn = __ldg(&d_bn[blockIdx.x]);

    __shared__ __align__(16) float As[64 * 68];
    __shared__ __align__(16) float Ws[64 * 68];
    __shared__ __align__(16) float sfv[8][4][64];
    int t = threadIdx.x;
    const float* wv = Wv + li * 4096;

    for (int idx = t; idx < 4096; idx += 256) {
        int r = idx >> 6, c = idx & 63;
        As[r * 68 + c] = d_A[idx];
        Ws[r * 68 + c] = __ldg(&wv[idx]);
    }
    __syncthreads();

    int wid = t >> 5, lane = t & 31;

    int pts[4];
    bool valid[4];
#pragma unroll
    for (int q = 0; q < 4; q++) {
        int idx = wid * 4 + q;
        valid[q] = idx < bn;
        int src = bstart + (valid[q] ? idx : 0);
        int pt = __ldg(&d_order[src]);
        pts[q] = pt;
        float2 fv = *(const float2*)&d_fT[pt * 64 + lane * 2];
        sfv[wid][q][lane * 2] = fv.x;
        sfv[wid][q][lane * 2 + 1] = fv.y;
    }
    __syncwarp();

    // class-uniform tables
    float pbl = __ldg(&d_pb[cls * 32 + lane]);
    float mi = 0.f, Si = 0.f, Ei = 0.f;
    if (lane < 16) {
        mi = __ldg(&d_m[cls * 16 + lane]);
        Si = __ldg(&d_S16[cls * 16 + lane]);
        Ei = __ldg(&d_Eii[cls * 16 + lane]);
    }
    float gl0 = __ldg(&d_gvec[lane]);
    float gl1 = __ldg(&d_gvec[lane + 32]);
    float c0v = d_c0;
    float bv0 = __ldg(&bv[li * 64 + lane]);
    float bv1 = __ldg(&bv[li * 64 + lane + 32]);

    // main matvecs: u = A.f, v = Wv.f  (f32x2-packed)
    ull u0[4] = {0, 0, 0, 0}, u1[4] = {0, 0, 0, 0};
    ull v0[4] = {0, 0, 0, 0}, v1[4] = {0, 0, 0, 0};
    const float* A0 = &As[lane * 68];
    const float* A1 = &As[(lane + 32) * 68];
    const float* W0 = &Ws[lane * 68];
    const float* W1 = &Ws[(lane + 32) * 68];
#pragma unroll
    for (int c = 0; c < 64; c += 4) {
        float4 a0 = *(const float4*)(A0 + c);
        float4 a1 = *(const float4*)(A1 + c);
        float4 b0 = *(const float4*)(W0 + c);
        float4 b1 = *(const float4*)(W1 + c);
        ull a0l = pk2(a0.x, a0.y), a0h = pk2(a0.z, a0.w);
        ull a1l = pk2(a1.x, a1.y), a1h = pk2(a1.z, a1.w);
        ull w0l = pk2(b0.x, b0.y), w0h = pk2(b0.z, b0.w);
        ull w1l = pk2(b1.x, b1.y), w1h = pk2(b1.z, b1.w);
#pragma unroll
        for (int q = 0; q < 4; q++) {
            float4 f = *(const float4*)&sfv[wid][q][c];
            ull fl = pk2(f.x, f.y), fh = pk2(f.z, f.w);
            u0[q] = f2fma(a0l, fl, u0[q]); u0[q] = f2fma(a0h, fh, u0[q]);
            u1[q] = f2fma(a1l, fl, u1[q]); u1[q] = f2fma(a1h, fh, u1[q]);
            v0[q] = f2fma(w0l, fl, v0[q]); v0[q] = f2fma(w0h, fh, v0[q]);
            v1[q] = f2fma(w1l, fl, v1[q]); v1[q] = f2fma(w1h, fh, v1[q]);
        }
    }

    float qk[4], v0f[4], v1f[4];
#pragma unroll
    for (int q = 0; q < 4; q++) {
        float2 uu0 = unpk(u0[q]), uu1 = unpk(u1[q]);
        float2 vv0 = unpk(v0[q]), vv1 = unpk(v1[q]);
        v0f[q] = vv0.x + vv0.y;
        v1f[q] = vv1.x + vv1.y;
        float fl0 = sfv[wid][q][lane];
        float fl1 = sfv[wid][q][lane + 32];
        float part = (uu0.x + uu0.y + gl0) * fl0 + (uu1.x + uu1.y + gl1) * fl1;
#pragma unroll
        for (int off = 16; off; off >>= 1) part += __shfl_xor_sync(0xffffffffu, part, off);
        qk[q] = part + c0v;   // Q_c . K_c
    }

    // cross terms: shared PR loads across the 4 points (c-major, 1-line LDGs)
    const float* PRb = &d_PR[cls * 2048];
    float dotq[4] = {pbl, pbl, pbl, pbl};
#pragma unroll 4
    for (int c = 0; c < 64; c += 4) {
        float p0 = __ldg(&PRb[c * 32 + lane]);
        float p1 = __ldg(&PRb[(c + 1) * 32 + lane]);
        float p2 = __ldg(&PRb[(c + 2) * 32 + lane]);
        float p3 = __ldg(&PRb[(c + 3) * 32 + lane]);
#pragma unroll
        for (int q = 0; q < 4; q++) {
            float4 f = *(const float4*)&sfv[wid][q][c];
            dotq[q] += p0 * f.x + p1 * f.y + p2 * f.z + p3 * f.w;
        }
    }

    float dval[4], d16[4];
#pragma unroll
    for (int q = 0; q < 4; q++) {
        float dot = dotq[q];
        float dv = 0.f;
        if (lane < 16) dv = Ei / (Si + __expf(dot - mi));
        dval[q] = dv;
        float hv = (lane >= 16) ? dot : -1e30f;
#pragma unroll
        for (int off = 16; off; off >>= 1) hv = fmaxf(hv, __shfl_xor_sync(0xffffffffu, hv, off));
        float m16 = fmaxf(hv, qk[q]);
        float ev = (lane >= 16) ? __expf(dot - m16) : 0.f;
#pragma unroll
        for (int off = 16; off; off >>= 1) ev += __shfl_xor_sync(0xffffffffu, ev, off);
        float eq = __expf(qk[q] - m16);
        d16[q] = eq / (ev + eq);
    }

    // output accumulation: shared Vw loads across the 4 points
    ull oa[4];
#pragma unroll
    for (int q = 0; q < 4; q++) oa[q] = pk2(d16[q] * (v0f[q] + bv0), d16[q] * (v1f[q] + bv1));
    const float2* Vb = (const float2*)&d_Vw[cls * 1024];
#pragma unroll
    for (int i = 0; i < 16; i++) {
        float2 vb = __ldg(&Vb[i * 32 + lane]);
        ull vbp = pk2(vb.x, vb.y);
#pragma unroll
        for (int q = 0; q < 4; q++) {
            float di = __shfl_sync(0xffffffffu, dval[q], i);
            oa[q] = f2fma(vbp, pk2(di, di), oa[q]);
        }
    }
#pragma unroll
    for (int q = 0; q < 4; q++) {
        if (valid[q]) {
            float2 o = unpk(oa[q]);
            d_x[pts[q] * 64 + lane] = o.x;
            d_x[pts[q] * 64 + lane + 32] = o.y;
        }
    }
}

// ------------------------- k3a/k3b: deterministic batch-norm stats -------------------------
__global__ void k3a() {
    int t = threadIdx.x;
    int c = t & 63, g = t >> 6;
    int p0 = blockIdx.x * 512;
    float s = 0.f, sq = 0.f;
    for (int k = 0; k < 128; k++) {
        float v = d_x[(p0 + g + k * 4) * 64 + c];
        s += v;
        sq += v * v;
    }
    __shared__ float shs[256], shq[256];
    shs[t] = s;
    shq[t] = sq;
    __syncthreads();
    if (t < 64) {
        float S = shs[t] + shs[t + 64] + shs[t + 128] + shs[t + 192];
        float Q = shq[t] + shq[t + 64] + shq[t + 128] + shq[t + 192];
        d_psum[t * 128 + blockIdx.x] = S;
        d_psq[t * 128 + blockIdx.x] = Q;
    }
}

__global__ void k3b(const float* __restrict__ gamma, const float* __restrict__ beta, int li) {
    int c = threadIdx.x;
    if (c < 64) {
        float S = 0.f, Q = 0.f;
        for (int k = 0; k < 128; k++) {
            S += d_psum[c * 128 + k];
            Q += d_psq[c * 128 + k];
        }
        float mean = S * (1.f / 65536.f);
        float var = Q * (1.f / 65536.f) - mean * mean;
        float sc = gamma[li * 64 + c] / sqrtf(var + 1e-5f);
        d_scale[c] = sc;
        d_shift[c] = beta[li * 64 + c] - sc * mean;
    }
}

// ------------------------- k4: norm + relu + residual; write d_out slice + update fT -------------------------
__global__ void k4(float* __restrict__ out, int li) {
    int p0 = blockIdx.x * 32;
    int b = p0 >> 15, n0 = p0 & 32767;
    __shared__ float sh[64 * 33];
    int t = threadIdx.x;
#pragma unroll
    for (int k = 0; k < 8; k++) {
        int idx = t + k * 256;            // 2048 = 32pts x 64c
        int p = idx >> 6, c = idx & 63;
        int a = (p0 + p) * 64 + c;
        float xv = d_x[a];
        float fo = d_fT[a];
        float y = fmaxf(d_scale[c] * xv + d_shift[c], 0.f);
        float fn = fo + y;
        d_fT[a] = fn;
        sh[c * 33 + p] = fn;
    }
    __syncthreads();
    int r = t >> 5, col = t & 31;
#pragma unroll
    for (int k = 0; k < 8; k++) {
        int c = r + k * 8;
        out[((size_t)(b * 192 + li * 64 + c)) * NN + n0 + col] = sh[c * 33 + col];
    }
}

// ------------------------- launch -------------------------
extern "C" void kernel_launch(void* const* d_in, const int* in_sizes, int n_in,
                              void* d_out, int out_size) {
    const float* feature = (const float*)d_in[0];
    const int*   knn     = (const int*)d_in[1];
    const float* Wq      = (const float*)d_in[2];
    const float* bq      = (const float*)d_in[3];
    const float* Wk      = (const float*)d_in[4];
    const float* bk      = (const float*)d_in[5];
    const float* Wv      = (const float*)d_in[6];
    const float* bv      = (const float*)d_in[7];
    const float* gamma   = (const float*)d_in[8];
    const float* beta    = (const float*)d_in[9];
    float* out = (float*)d_out;

    kT<<<2048, 256>>>(feature);
    k0<<<8192, 256>>>(knn);
    khist<<<64, 256>>>();
    kscan<<<1, 32>>>();
    kscatter<<<64, 256>>>();
    for (int li = 0; li < 3; li++) {
        kPre<<<64, 256>>>(Wq, bq, Wk, bk, Wv, bv, li);
        k2<<<NBLK2, 256>>>(Wv, bv, li);
        k3a<<<128, 256>>>();
        k3b<<<1, 64>>>(gamma, beta, li);
        k4<<<2048, 256>>>(out, li);
    }
}